// round 3
// baseline (speedup 1.0000x reference)
#include <cuda_runtime.h>
#include <cuda_bf16.h>

// BitConv2dInfer: y = conv2d(x, ternary_w) * s + bias
// x:[32,128,56,56] f32, w_q:[256,128,3,3] ternary (delivered dtype unknown:
// int8 / int32 / float32 -- probed at runtime), s:[256], bias:[256]
// out:[32,256,56,56] f32

#define CIN       128
#define COUT      256
#define HH        56
#define WW        56
#define CO_TILE   64
#define PT        8      // pixel tile edge
#define CK        16     // c_in chunk

// 0 = int8, 1 = int32, 2 = float32
__device__ int g_wtype;

// Probe the weight buffer's dtype. Reads only the first 1024 bytes, which is
// in-bounds for every candidate interpretation (int8 buffer = 294912 bytes).
// Ternary data makes the three interpretations mutually exclusive:
//   f32 {-1,0,1}: bit patterns 0x00000000 / 0x3F800000 / 0xBF800000
//   i32 {-1,0,1}: 0x00000000 / 0x00000001 / 0xFFFFFFFF
//   i8 packed quads reinterpreted never form 0x3F800000; i32 +/-1 as float is
//   denormal/NaN. Deterministic, recomputed every call.
__global__ void probe_wtype_kernel(const void* __restrict__ wq)
{
    if (threadIdx.x != 0 || blockIdx.x != 0) return;
    const float* wf = (const float*)wq;
    const int*   wi = (const int*)wq;
    bool is_f32 = true, is_i32 = true;
    for (int i = 0; i < 256; i++) {
        float fv = wf[i];
        if (!(fv == -1.0f || fv == 0.0f || fv == 1.0f)) is_f32 = false;
        int iv = wi[i];
        if (!(iv == -1 || iv == 0 || iv == 1)) is_i32 = false;
    }
    g_wtype = is_f32 ? 2 : (is_i32 ? 1 : 0);
}

__global__ __launch_bounds__(256, 2)
void bitconv_fp32_kernel(const float* __restrict__ x,
                         const void* __restrict__ wq,
                         const float* __restrict__ s,
                         const float* __restrict__ bias,
                         float* __restrict__ out)
{
    __shared__ float sX[CK * 10 * 10];          // 6.4 KB halo tile
    __shared__ float sW[CK * 9 * CO_TILE];      // 36.9 KB, layout [ci][k][co]

    const int tile    = blockIdx.x;             // 0..48 (7x7 tiles of 8x8)
    const int h0      = (tile / 7) * PT;
    const int w0      = (tile % 7) * PT;
    const int co_base = blockIdx.y * CO_TILE;
    const int n       = blockIdx.z;

    const int t       = threadIdx.x;
    const int co_sub  = t >> 4;                 // 0..15 -> 4 c_out each
    const int pix_sub = t & 15;                 // 0..15 -> 4 pixels each
    const int prow    = pix_sub >> 1;           // 0..7
    const int pcol0   = (pix_sub & 1) * 4;      // 0 or 4

    const int wt = g_wtype;                     // uniform across grid
    const signed char* w8  = (const signed char*)wq;
    const int*         w32 = (const int*)wq;
    const float*       wf  = (const float*)wq;

    float acc[4][4] = {};

    const float* xn = x + (size_t)n * CIN * HH * WW;

    for (int ci0 = 0; ci0 < CIN; ci0 += CK) {
        __syncthreads();   // protect smem reuse from previous iteration

        // ---- stage input halo tile: CK x 10 x 10, zero-padded ----
        for (int i = t; i < CK * 100; i += 256) {
            int ci  = i / 100;
            int rem = i - ci * 100;
            int r   = rem / 10;
            int c   = rem - r * 10;
            int gh  = h0 - 1 + r;
            int gw  = w0 - 1 + c;
            float v = 0.0f;
            if ((unsigned)gh < HH && (unsigned)gw < WW)
                v = xn[((size_t)(ci0 + ci) * HH + gh) * WW + gw];
            sX[i] = v;
        }

        // ---- stage weights -> f32, layout [ci][k][co], dtype-adaptive ----
        for (int i = t; i < CK * 9 * CO_TILE; i += 256) {
            int co   = i & (CO_TILE - 1);
            int rest = i >> 6;               // ci*9 + k
            int ci   = rest / 9;
            int k    = rest - ci * 9;
            size_t gidx = (((size_t)(co_base + co)) * CIN + (ci0 + ci)) * 9 + k;
            float v;
            if (wt == 0)      v = (float)w8[gidx];
            else if (wt == 1) v = (float)w32[gidx];
            else              v = wf[gidx];
            sW[i] = v;
        }
        __syncthreads();

        // ---- compute: 4x4 register tile per thread ----
        #pragma unroll 4
        for (int ci = 0; ci < CK; ci++) {
            #pragma unroll
            for (int kh = 0; kh < 3; kh++) {
                const float* xr = &sX[ci * 100 + (prow + kh) * 10 + pcol0];
                #pragma unroll
                for (int kw = 0; kw < 3; kw++) {
                    float4 w4 = *(const float4*)&sW[(ci * 9 + kh * 3 + kw) * CO_TILE + co_sub * 4];
                    float wv[4] = {w4.x, w4.y, w4.z, w4.w};
                    float xv[4];
                    #pragma unroll
                    for (int j = 0; j < 4; j++) xv[j] = xr[kw + j];
                    #pragma unroll
                    for (int i = 0; i < 4; i++)
                        #pragma unroll
                        for (int j = 0; j < 4; j++)
                            acc[i][j] = fmaf(wv[i], xv[j], acc[i][j]);
                }
            }
        }
    }

    // ---- epilogue: *s + bias, float4 stores (in-bounds by construction) ----
    #pragma unroll
    for (int i = 0; i < 4; i++) {
        int co = co_base + co_sub * 4 + i;
        float sv = s[co];
        float bv = bias[co];
        float4 o;
        o.x = acc[i][0] * sv + bv;
        o.y = acc[i][1] * sv + bv;
        o.z = acc[i][2] * sv + bv;
        o.w = acc[i][3] * sv + bv;
        float* orow = out + (((size_t)n * COUT + co) * HH + (h0 + prow)) * WW + (w0 + pcol0);
        *(float4*)orow = o;
    }
}

extern "C" void kernel_launch(void* const* d_in, const int* in_sizes, int n_in,
                              void* d_out, int out_size)
{
    const float* xp = (const float*)d_in[0];
    const void*  wp = d_in[1];
    const float* sp = (const float*)d_in[2];
    const float* bp = (const float*)d_in[3];
    float*       op = (float*)d_out;

    probe_wtype_kernel<<<1, 32>>>(wp);

    dim3 grid(49, COUT / CO_TILE, 32);   // (7x7 tiles, 4 co tiles, 32 batch)
    dim3 block(256);
    bitconv_fp32_kernel<<<grid, block>>>(xp, wp, sp, bp, op);
}

// round 4
// speedup vs baseline: 1.9401x; 1.9401x over previous
#include <cuda_runtime.h>
#include <cuda_bf16.h>

// BitConv2dInfer: y = conv2d(x, ternary_w) * s + bias
// x:[32,128,56,56] f32, w_q:[256,128,3,3] ternary (dtype probed at runtime),
// s:[256], bias:[256], out:[32,256,56,56] f32
//
// R3: register-tile widened to 4co x 8pix per thread; x row loaded once per
// (ci,kh) as 3x LDS.128 (12-float padded rows, conflict-free), slid across kw.
// LDS/FMA ratio drops 5x vs R2 (which was L1-bound at 97%).

#define CIN       128
#define COUT      256
#define HH        56
#define WW        56
#define CO_TILE   64
#define PT        8
#define CK        16
#define XROW      12    // padded row width (10 used + 2 pad) -> 48B, float4-aligned

// 0 = int8, 1 = int32, 2 = float32
__device__ int g_wtype;

__global__ void probe_wtype_kernel(const void* __restrict__ wq)
{
    if (threadIdx.x != 0 || blockIdx.x != 0) return;
    const float* wf = (const float*)wq;
    const int*   wi = (const int*)wq;
    bool is_f32 = true, is_i32 = true;
    for (int i = 0; i < 256; i++) {
        float fv = wf[i];
        if (!(fv == -1.0f || fv == 0.0f || fv == 1.0f)) is_f32 = false;
        int iv = wi[i];
        if (!(iv == -1 || iv == 0 || iv == 1)) is_i32 = false;
    }
    g_wtype = is_f32 ? 2 : (is_i32 ? 1 : 0);
}

__global__ __launch_bounds__(128, 4)
void bitconv_fp32_v2(const float* __restrict__ x,
                     const void* __restrict__ wq,
                     const float* __restrict__ s,
                     const float* __restrict__ bias,
                     float* __restrict__ out)
{
    __shared__ float sX[CK * 10 * XROW];        // 16 x 10 x 12 f32 = 7.5 KB
    __shared__ float sW[CK * 9 * CO_TILE];      // 36 KB, layout [ci][k][co]

    const int tile    = blockIdx.x;             // 0..48
    const int h0      = (tile / 7) * PT;
    const int w0      = (tile % 7) * PT;
    const int co_base = blockIdx.y * CO_TILE;
    const int n       = blockIdx.z;

    const int t   = threadIdx.x;                // 0..127
    const int row = t & 7;                      // pixel row within tile
    const int cg  = t >> 3;                     // 0..15, 4 c_out each

    const int wt = g_wtype;
    const signed char* w8  = (const signed char*)wq;
    const int*         w32 = (const int*)wq;
    const float*       wf  = (const float*)wq;

    float acc[4][8];
    #pragma unroll
    for (int i = 0; i < 4; i++)
        #pragma unroll
        for (int j = 0; j < 8; j++) acc[i][j] = 0.0f;

    const float* xn = x + (size_t)n * CIN * HH * WW;

    for (int ci0 = 0; ci0 < CIN; ci0 += CK) {
        __syncthreads();

        // ---- stage input halo: CK x 10 x 12 (cols 10,11 zero-pad) ----
        for (int i = t; i < CK * 10 * XROW; i += 128) {
            int ci  = i / (10 * XROW);
            int rem = i - ci * (10 * XROW);
            int r   = rem / XROW;
            int c   = rem - r * XROW;
            int gh  = h0 - 1 + r;
            int gw  = w0 - 1 + c;
            float v = 0.0f;
            if (c < 10 && (unsigned)gh < HH && (unsigned)gw < WW)
                v = xn[((size_t)(ci0 + ci) * HH + gh) * WW + gw];
            sX[i] = v;
        }

        // ---- stage weights -> f32, layout [ci][k][co], dtype-adaptive ----
        for (int i = t; i < CK * 9 * CO_TILE; i += 128) {
            int co   = i & (CO_TILE - 1);
            int rest = i >> 6;               // ci*9 + k
            int ci   = rest / 9;
            int k    = rest - ci * 9;
            size_t gidx = (((size_t)(co_base + co)) * CIN + (ci0 + ci)) * 9 + k;
            float v;
            if (wt == 0)      v = (float)w8[gidx];
            else if (wt == 1) v = (float)w32[gidx];
            else              v = wf[gidx];
            sW[i] = v;
        }
        __syncthreads();

        // ---- compute: 4co x 8pix per thread ----
        #pragma unroll 2
        for (int ci = 0; ci < CK; ci++) {
            #pragma unroll
            for (int kh = 0; kh < 3; kh++) {
                const float* xr = &sX[(ci * 10 + row + kh) * XROW];
                float4 xa = *(const float4*)(xr);
                float4 xb = *(const float4*)(xr + 4);
                float4 xc = *(const float4*)(xr + 8);
                float xv[12] = {xa.x, xa.y, xa.z, xa.w,
                                xb.x, xb.y, xb.z, xb.w,
                                xc.x, xc.y, xc.z, xc.w};
                #pragma unroll
                for (int kw = 0; kw < 3; kw++) {
                    float4 w4 = *(const float4*)&sW[(ci * 9 + kh * 3 + kw) * CO_TILE + cg * 4];
                    float wv[4] = {w4.x, w4.y, w4.z, w4.w};
                    #pragma unroll
                    for (int i = 0; i < 4; i++)
                        #pragma unroll
                        for (int j = 0; j < 8; j++)
                            acc[i][j] = fmaf(wv[i], xv[kw + j], acc[i][j]);
                }
            }
        }
    }

    // ---- epilogue: *s + bias, 2x float4 stores per co ----
    #pragma unroll
    for (int i = 0; i < 4; i++) {
        int co = co_base + cg * 4 + i;
        float sv = s[co];
        float bv = bias[co];
        float* orow = out + (((size_t)n * COUT + co) * HH + (h0 + row)) * WW + w0;
        float4 o0, o1;
        o0.x = acc[i][0] * sv + bv;  o0.y = acc[i][1] * sv + bv;
        o0.z = acc[i][2] * sv + bv;  o0.w = acc[i][3] * sv + bv;
        o1.x = acc[i][4] * sv + bv;  o1.y = acc[i][5] * sv + bv;
        o1.z = acc[i][6] * sv + bv;  o1.w = acc[i][7] * sv + bv;
        *(float4*)(orow)     = o0;
        *(float4*)(orow + 4) = o1;
    }
}

extern "C" void kernel_launch(void* const* d_in, const int* in_sizes, int n_in,
                              void* d_out, int out_size)
{
    const float* xp = (const float*)d_in[0];
    const void*  wp = d_in[1];
    const float* sp = (const float*)d_in[2];
    const float* bp = (const float*)d_in[3];
    float*       op = (float*)d_out;

    probe_wtype_kernel<<<1, 32>>>(wp);

    dim3 grid(49, COUT / CO_TILE, 32);
    dim3 block(128);
    bitconv_fp32_v2<<<grid, block>>>(xp, wp, sp, bp, op);
}

// round 6
// speedup vs baseline: 10.0624x; 5.1865x over previous
#include <cuda_runtime.h>
#include <cuda_bf16.h>
#include <cstdint>

// BitConv2dInfer via warp-level HMMA (mma.sync bf16, sm_80+ portable PTX):
// y = conv2d(x, ternary_w) * s + bias
// x:[32,128,56,56] f32, w ternary (dtype probed), s:[256], bias:[256]
// out:[32,256,56,56] f32
//
// Implicit GEMM, shifted-window: D[pixel,co] += xsplit[pixel,ci]*w[co,ci]
// per (kh,kw). bf16 hi/lo split of x -> fp32-accurate (rel_err ~1e-5).
// CTA: M=256 pixels (4 rows x 64 padded cols) x N=64 co. 8 warps 4x2,
// warp tile 64x32 (4 mtiles x 4 ntiles of m16n8k16).

#define CIN   128
#define COUT  256
#define HH    56
#define WW    56
#define HHWW  (HH * WW)

// smem byte offsets (48B-padded rows everywhere -> conflict-free ldmatrix)
#define SW_OFF     0         // weights: 9 * 64co * 48B            = 27648
#define SA_OFF     27648     // x patch: 2 splits * 6r * 68c * 48B = 39168
#define SA_SPLIT   19584     //   per-split bytes
#define SS_OFF     66816     // s[64]
#define SBIAS_OFF  67072     // bias[64]
#define SMEM_TOTAL 67328

#define LDSM4(r, a) \
    asm volatile("ldmatrix.sync.aligned.m8n8.x4.shared.b16 {%0,%1,%2,%3}, [%4];" \
        : "=r"((r)[0]), "=r"((r)[1]), "=r"((r)[2]), "=r"((r)[3]) : "r"(a))

#define MMA16816(c, a, b0, b1) \
    asm volatile("mma.sync.aligned.m16n8k16.row.col.f32.bf16.bf16.f32 " \
        "{%0,%1,%2,%3}, {%4,%5,%6,%7}, {%8,%9}, {%0,%1,%2,%3};" \
        : "+f"((c)[0]), "+f"((c)[1]), "+f"((c)[2]), "+f"((c)[3]) \
        : "r"((a)[0]), "r"((a)[1]), "r"((a)[2]), "r"((a)[3]), "r"(b0), "r"(b1))

__device__ __forceinline__ uint32_t smem_u32(const void* p) {
    uint32_t a;
    asm("{ .reg .u64 t; cvta.to.shared.u64 t, %1; cvt.u32.u64 %0, t; }" : "=r"(a) : "l"(p));
    return a;
}

// ---------------- weight probe + prepass ----------------
__device__ int g_wtype;    // 0=int8, 1=int32, 2=float32
// bf16 weight image: [chunk 8][cogroup 4][khkw 9][co 64][ci 24pad] (884 KB)
__device__ __align__(16) __nv_bfloat16 g_wbf[8 * 4 * 9 * 64 * 24];

__global__ void probe_kernel(const void* __restrict__ wq) {
    int lane = threadIdx.x;
    const float* wf = (const float*)wq;
    const int*   wi = (const int*)wq;
    bool f32ok = true, i32ok = true;
    for (int i = lane; i < 256; i += 32) {
        float fv = wf[i];
        if (!(fv == -1.0f || fv == 0.0f || fv == 1.0f)) f32ok = false;
        int iv = wi[i];
        if (!(iv == -1 || iv == 0 || iv == 1)) i32ok = false;
    }
    unsigned bf = __ballot_sync(0xFFFFFFFFu, f32ok);
    unsigned bi = __ballot_sync(0xFFFFFFFFu, i32ok);
    if (lane == 0) g_wtype = (bf == 0xFFFFFFFFu) ? 2 : ((bi == 0xFFFFFFFFu) ? 1 : 0);
}

__global__ void prepass_kernel(const void* __restrict__ wq) {
    int e = blockIdx.x * 256 + threadIdx.x;       // e = (co*CIN + ci)*9 + khkw
    if (e >= COUT * CIN * 9) return;
    int khkw = e % 9;
    int t2   = e / 9;
    int ci   = t2 % CIN;
    int co   = t2 / CIN;
    int wt = g_wtype;
    float v;
    if (wt == 0)      v = (float)((const signed char*)wq)[e];
    else if (wt == 1) v = (float)((const int*)wq)[e];
    else              v = ((const float*)wq)[e];
    int dst = ((((ci >> 4) * 4 + (co >> 6)) * 9 + khkw) * 64 + (co & 63)) * 24 + (ci & 15);
    g_wbf[dst] = __float2bfloat16(v);
}

// ---------------- main HMMA kernel ----------------
__global__ void __launch_bounds__(256, 2)
bitconv_hmma_kernel(const float* __restrict__ x,
                    const float* __restrict__ s,
                    const float* __restrict__ bias,
                    float* __restrict__ out)
{
    extern __shared__ char smem[];
    const uint32_t smb = smem_u32(smem);
    const int t   = threadIdx.x;
    const int wid = t >> 5;
    const int lid = t & 31;
    const int wm  = wid >> 1;          // 0..3 -> output row within CTA
    const int wn  = wid & 1;           // 0..1 -> 32-co half

    const int h0     = blockIdx.x * 4;            // 14 row-quads
    const int cog    = blockIdx.y;                // 0..3 cogroup (64 co)
    const int cobase = cog * 64;
    const int n      = blockIdx.z;

    // stage s / bias for this cogroup
    if (t < 64) {
        ((float*)(smem + SS_OFF))[t]    = s[cobase + t];
        ((float*)(smem + SBIAS_OFF))[t] = bias[cobase + t];
    }

    float acc[4][4][4];
    #pragma unroll
    for (int a = 0; a < 4; a++)
        #pragma unroll
        for (int b = 0; b < 4; b++)
            #pragma unroll
            for (int c = 0; c < 4; c++) acc[a][b][c] = 0.0f;

    const float* xn = x + (size_t)n * CIN * HHWW;

    // precompute per-lane ldmatrix address components
    const int a_row   = lid & 15;                 // pixel-within-mtile
    const int a_kb16  = (lid >> 4) * 16;          // k-block byte offset
    const int b_grp   = lid >> 3;                 // 0..3
    const int b_co    = ((b_grp >= 2) ? 8 : 0) + (lid & 7);
    const int b_kb16  = (b_grp & 1) * 16;

    #pragma unroll 1
    for (int chunk = 0; chunk < 8; chunk++) {
        __syncthreads();

        // ---- stage weights: contiguous 27648B slab (L2-resident) ----
        {
            const uint4* src = (const uint4*)((const char*)g_wbf +
                                (size_t)(chunk * 4 + cog) * 27648);
            uint4* dst = (uint4*)(smem + SW_OFF);
            for (int i = t; i < 1728; i += 256) dst[i] = src[i];
        }

        // ---- stage x patch: 6 rows x 68 cols x 16 ci, hi/lo bf16 ----
        {
            const int ci0 = chunk * 16;
            __nv_bfloat16* sa0 = (__nv_bfloat16*)(smem + SA_OFF);
            __nv_bfloat16* sa1 = (__nv_bfloat16*)(smem + SA_OFF + SA_SPLIT);
            for (int i = t; i < 6528; i += 256) {   // 16 ci * 408 positions
                int ci = i / 408;
                int p  = i - ci * 408;              // p = r*68 + c
                int r  = p / 68;
                int c  = p - r * 68;
                int gh = h0 - 1 + r;
                int gw = c - 1;
                float v = 0.0f;
                if ((unsigned)gh < HH && (unsigned)gw < WW)
                    v = xn[((size_t)(ci0 + ci) * HH + gh) * WW + gw];
                __nv_bfloat16 hi = __float2bfloat16(v);
                __nv_bfloat16 lo = __float2bfloat16(v - __bfloat162float(hi));
                int el = p * 24 + ci;
                sa0[el] = hi;
                sa1[el] = lo;
            }
        }
        __syncthreads();

        // ---- compute: 9 shifts x 2 splits x 4 mtiles x 4 ntiles ----
        #pragma unroll 1
        for (int khkw = 0; khkw < 9; khkw++) {
            const int kh = khkw / 3;
            const int kw = khkw - 3 * kh;

            uint32_t bfr[2][4];
            #pragma unroll
            for (int pr2 = 0; pr2 < 2; pr2++) {
                uint32_t addr = smb + SW_OFF +
                    (uint32_t)((khkw * 64 + wn * 32 + pr2 * 16 + b_co) * 48 + b_kb16);
                LDSM4(bfr[pr2], addr);
            }

            #pragma unroll
            for (int sp = 0; sp < 2; sp++) {
                const uint32_t abase = smb + SA_OFF + sp * SA_SPLIT +
                    (uint32_t)(((wm + kh) * 68 + a_row + kw) * 48 + a_kb16);
                #pragma unroll
                for (int mt = 0; mt < 4; mt++) {
                    uint32_t afr[4];
                    LDSM4(afr, abase + (uint32_t)(mt * 16 * 48));
                    #pragma unroll
                    for (int nt = 0; nt < 4; nt++)
                        MMA16816(acc[mt][nt], afr,
                                 bfr[nt >> 1][(nt & 1) * 2],
                                 bfr[nt >> 1][(nt & 1) * 2 + 1]);
                }
            }
        }
    }

    // ---- epilogue: *s + bias ----
    {
        const float* ss = (const float*)(smem + SS_OFF);
        const float* sb = (const float*)(smem + SBIAS_OFF);
        const int h  = h0 + wm;
        const int r0 = lid >> 2;
        const int c0 = (lid & 3) * 2;
        #pragma unroll
        for (int mt = 0; mt < 4; mt++) {
            int pc0 = mt * 16 + r0;         // always < 56
            int pc1 = pc0 + 8;              // invalid only when mt==3
            #pragma unroll
            for (int nt = 0; nt < 4; nt++) {
                int col = wn * 32 + nt * 8 + c0;       // local co
                int co  = cobase + col;
                float sv0 = ss[col],     bv0 = sb[col];
                float sv1 = ss[col + 1], bv1 = sb[col + 1];
                size_t base0 = (((size_t)n * COUT + co) * HH + h) * WW;
                out[base0 + pc0]        = acc[mt][nt][0] * sv0 + bv0;
                out[base0 + HHWW + pc0] = acc[mt][nt][1] * sv1 + bv1;
                if (pc1 < WW) {
                    out[base0 + pc1]        = acc[mt][nt][2] * sv0 + bv0;
                    out[base0 + HHWW + pc1] = acc[mt][nt][3] * sv1 + bv1;
                }
            }
        }
    }
}

extern "C" void kernel_launch(void* const* d_in, const int* in_sizes, int n_in,
                              void* d_out, int out_size)
{
    const float* xp = (const float*)d_in[0];
    const void*  wp = d_in[1];
    const float* sp = (const float*)d_in[2];
    const float* bp = (const float*)d_in[3];
    float*       op = (float*)d_out;

    cudaFuncSetAttribute(bitconv_hmma_kernel,
                         cudaFuncAttributeMaxDynamicSharedMemorySize, SMEM_TOTAL);

    probe_kernel<<<1, 32>>>(wp);
    prepass_kernel<<<(COUT * CIN * 9 + 255) / 256, 256>>>(wp);

    dim3 grid(HH / 4, COUT / 64, 32);   // (row-quads, cogroups, batch)
    bitconv_hmma_kernel<<<grid, 256, SMEM_TOTAL>>>(xp, sp, bp, op);
}

// round 7
// speedup vs baseline: 23.1944x; 2.3051x over previous
#include <cuda_runtime.h>
#include <cuda_fp16.h>
#include <cstdint>

// BitConv2dInfer via warp-level HMMA fp16 (mma.sync, sm_80+ portable PTX):
// y = conv2d(x, ternary_w) * s + bias
// x:[32,128,56,56] f32, w ternary (dtype probed), s:[256], bias:[256]
// out:[32,256,56,56] f32
//
// R6: fp16 single-pass (w exact in fp16; x rounding -> rel_err ~3e-4),
// x pre-transposed to NHWC fp16 so A staging is contiguous cp.async,
// double-buffered chunk pipeline.

#define CIN   128
#define COUT  256
#define HH    56
#define WW    56
#define HHWW  (HH * WW)

// per-buffer smem layout (48B-padded rows -> conflict-free ldmatrix)
#define WBYTES     27648     // weights: 9 * 64co * 48B
#define ABYTES     19584     // x patch: 6r * 68c * 48B
#define BUFBYTES   (WBYTES + ABYTES)          // 47232
#define SS_OFF     (2 * BUFBYTES)             // 94464
#define SBIAS_OFF  (SS_OFF + 256)
#define SMEM_TOTAL (SBIAS_OFF + 256)          // 94976

#define LDSM4(r, a) \
    asm volatile("ldmatrix.sync.aligned.m8n8.x4.shared.b16 {%0,%1,%2,%3}, [%4];" \
        : "=r"((r)[0]), "=r"((r)[1]), "=r"((r)[2]), "=r"((r)[3]) : "r"(a))

#define MMA16816(c, a, b0, b1) \
    asm volatile("mma.sync.aligned.m16n8k16.row.col.f32.f16.f16.f32 " \
        "{%0,%1,%2,%3}, {%4,%5,%6,%7}, {%8,%9}, {%0,%1,%2,%3};" \
        : "+f"((c)[0]), "+f"((c)[1]), "+f"((c)[2]), "+f"((c)[3]) \
        : "r"((a)[0]), "r"((a)[1]), "r"((a)[2]), "r"((a)[3]), "r"(b0), "r"(b1))

#define CP_ASYNC16(dst, src, sz) \
    asm volatile("cp.async.cg.shared.global [%0], [%1], 16, %2;" \
        :: "r"(dst), "l"(src), "r"(sz) : "memory")
#define CP_COMMIT() asm volatile("cp.async.commit_group;" ::: "memory")
#define CP_WAIT(n)  asm volatile("cp.async.wait_group %0;" :: "n"(n) : "memory")

__device__ __forceinline__ uint32_t smem_u32(const void* p) {
    uint32_t a;
    asm("{ .reg .u64 t; cvta.to.shared.u64 t, %1; cvt.u32.u64 %0, t; }" : "=r"(a) : "l"(p));
    return a;
}

// ---------------- scratch ----------------
__device__ int g_wtype;    // 0=int8, 1=int32, 2=float32
// fp16 weight image: [chunk 8][cogroup 4][khkw 9][co 64][ci 24pad]
__device__ __align__(16) __half g_wh[8 * 4 * 9 * 64 * 24];
// x transposed to NHWC fp16: [n][h][w][ci]
__device__ __align__(16) __half g_xh[(size_t)32 * HH * WW * CIN];

// ---------------- probe (parallel) ----------------
__global__ void probe_kernel(const void* __restrict__ wq) {
    int t = threadIdx.x;          // 256 threads, 1 elem each (1024B: in-bounds all dtypes)
    const float* wf = (const float*)wq;
    const int*   wi = (const int*)wq;
    float fv = wf[t];
    int   iv = wi[t];
    int f32ok = (fv == -1.0f || fv == 0.0f || fv == 1.0f);
    int i32ok = (iv == -1 || iv == 0 || iv == 1);
    int allf = __syncthreads_and(f32ok);
    int alli = __syncthreads_and(i32ok);
    if (t == 0) g_wtype = allf ? 2 : (alli ? 1 : 0);
}

// ---------------- weight prepass ----------------
__global__ void prepass_kernel(const void* __restrict__ wq) {
    int e = blockIdx.x * 256 + threadIdx.x;       // e = (co*CIN + ci)*9 + khkw
    if (e >= COUT * CIN * 9) return;
    int khkw = e % 9;
    int t2   = e / 9;
    int ci   = t2 % CIN;
    int co   = t2 / CIN;
    int wt = g_wtype;
    float v;
    if (wt == 0)      v = (float)((const signed char*)wq)[e];
    else if (wt == 1) v = (float)((const int*)wq)[e];
    else              v = ((const float*)wq)[e];
    int dst = ((((ci >> 4) * 4 + (co >> 6)) * 9 + khkw) * 64 + (co & 63)) * 24 + (ci & 15);
    g_wh[dst] = __float2half(v);
}

// ---------------- x NCHW f32 -> NHWC f16 ----------------
__global__ void __launch_bounds__(256, 4)
xprep_kernel(const float* __restrict__ x) {
    __shared__ float tile[CIN * 57];              // 57-pad -> conflict-free transpose read
    int b = blockIdx.x;
    int n = b / HH;
    int h = b - n * HH;
    int t = threadIdx.x;
    const float* src = x + ((size_t)n * CIN * HH + h) * WW;   // + ci*HHWW + w
    for (int i = t; i < CIN * WW; i += 256) {
        int ci = i / WW;
        int w  = i - ci * WW;
        tile[ci * 57 + w] = src[(size_t)ci * HHWW + w];
    }
    __syncthreads();
    __half* dst = g_xh + (((size_t)n * HH + h) * WW) * CIN;   // + w*CIN + ci
    for (int i = t; i < WW * CIN; i += 256) {
        int w  = i >> 7;
        int ci = i & 127;
        dst[i] = __float2half(tile[ci * 57 + w]);
    }
}

// ---------------- main HMMA kernel ----------------
__global__ void __launch_bounds__(256, 2)
bitconv_hmma_kernel(const float* __restrict__ s,
                    const float* __restrict__ bias,
                    float* __restrict__ out)
{
    extern __shared__ char smem[];
    const uint32_t smb = smem_u32(smem);
    const int t   = threadIdx.x;
    const int wid = t >> 5;
    const int lid = t & 31;
    const int wm  = wid >> 1;          // 0..3 -> output row within CTA
    const int wn  = wid & 1;           // 0..1 -> 32-co half

    const int h0     = blockIdx.x * 4;            // 14 row-quads
    const int cog    = blockIdx.y;                // 0..3 (64 co each)
    const int cobase = cog * 64;
    const int n      = blockIdx.z;

    if (t < 64) {
        ((float*)(smem + SS_OFF))[t]    = s[cobase + t];
        ((float*)(smem + SBIAS_OFF))[t] = bias[cobase + t];
    }

    float acc[4][4][4];
    #pragma unroll
    for (int a = 0; a < 4; a++)
        #pragma unroll
        for (int b = 0; b < 4; b++)
            #pragma unroll
            for (int c = 0; c < 4; c++) acc[a][b][c] = 0.0f;

    // per-lane ldmatrix address components
    const int a_row  = lid & 15;
    const int a_kb16 = (lid >> 4) * 16;
    const int b_grp  = lid >> 3;
    const int b_co   = ((b_grp >= 2) ? 8 : 0) + (lid & 7);
    const int b_kb16 = (b_grp & 1) * 16;

    // ---- staging lambda: weights + A patch via cp.async into buffer `buf` ----
    auto stage = [&](int chunk, int buf) {
        const uint32_t base = smb + buf * BUFBYTES;
        // weights: contiguous slab
        const char* wsrc = (const char*)g_wh + (size_t)(chunk * 4 + cog) * WBYTES;
        for (int i = t; i < WBYTES / 16; i += 256)
            CP_ASYNC16(base + i * 16, wsrc + i * 16, 16);
        // A patch: 408 pixel-rows x 2 halves, NHWC-contiguous 16B each
        const int ci0 = chunk * 16;
        for (int i = t; i < 816; i += 256) {
            int p    = i >> 1;
            int half = i & 1;
            int r    = p / 68;
            int c    = p - r * 68;
            int gh   = h0 - 1 + r;
            int gw   = c - 1;
            int valid = ((unsigned)gh < HH) & ((unsigned)gw < WW);
            const __half* src = g_xh +
                ((((size_t)n * HH + (valid ? gh : 0)) * WW + (valid ? gw : 0)) * CIN)
                + ci0 + half * 8;
            CP_ASYNC16(base + WBYTES + p * 48 + half * 16, src, valid ? 16 : 0);
        }
    };

    stage(0, 0);
    CP_COMMIT();

    #pragma unroll 1
    for (int chunk = 0; chunk < 8; chunk++) {
        if (chunk) __syncthreads();               // all warps done with buf[(chunk+1)&1]
        if (chunk + 1 < 8) { stage(chunk + 1, (chunk + 1) & 1); CP_COMMIT(); }
        if (chunk + 1 < 8) { CP_WAIT(1); } else { CP_WAIT(0); }
        __syncthreads();

        const uint32_t wbase = smb + (chunk & 1) * BUFBYTES;
        const uint32_t abase_all = wbase + WBYTES;

        #pragma unroll 1
        for (int khkw = 0; khkw < 9; khkw++) {
            const int kh = khkw / 3;
            const int kw = khkw - 3 * kh;

            uint32_t bfr[2][4];
            #pragma unroll
            for (int pr2 = 0; pr2 < 2; pr2++) {
                uint32_t addr = wbase +
                    (uint32_t)((khkw * 64 + wn * 32 + pr2 * 16 + b_co) * 48 + b_kb16);
                LDSM4(bfr[pr2], addr);
            }

            const uint32_t abase = abase_all +
                (uint32_t)(((wm + kh) * 68 + a_row + kw) * 48 + a_kb16);
            #pragma unroll
            for (int mt = 0; mt < 4; mt++) {
                uint32_t afr[4];
                LDSM4(afr, abase + (uint32_t)(mt * 16 * 48));
                #pragma unroll
                for (int nt = 0; nt < 4; nt++)
                    MMA16816(acc[mt][nt], afr,
                             bfr[nt >> 1][(nt & 1) * 2],
                             bfr[nt >> 1][(nt & 1) * 2 + 1]);
            }
        }
    }

    // ---- epilogue: *s + bias ----
    {
        const float* ss = (const float*)(smem + SS_OFF);
        const float* sb = (const float*)(smem + SBIAS_OFF);
        const int h  = h0 + wm;
        const int r0 = lid >> 2;
        const int c0 = (lid & 3) * 2;
        #pragma unroll
        for (int mt = 0; mt < 4; mt++) {
            int pc0 = mt * 16 + r0;         // always < 56
            int pc1 = pc0 + 8;              // invalid only when mt==3
            #pragma unroll
            for (int nt = 0; nt < 4; nt++) {
                int col = wn * 32 + nt * 8 + c0;
                int co  = cobase + col;
                float sv0 = ss[col],     bv0 = sb[col];
                float sv1 = ss[col + 1], bv1 = sb[col + 1];
                size_t base0 = (((size_t)n * COUT + co) * HH + h) * WW;
                out[base0 + pc0]        = acc[mt][nt][0] * sv0 + bv0;
                out[base0 + HHWW + pc0] = acc[mt][nt][1] * sv1 + bv1;
                if (pc1 < WW) {
                    out[base0 + pc1]        = acc[mt][nt][2] * sv0 + bv0;
                    out[base0 + HHWW + pc1] = acc[mt][nt][3] * sv1 + bv1;
                }
            }
        }
    }
}

extern "C" void kernel_launch(void* const* d_in, const int* in_sizes, int n_in,
                              void* d_out, int out_size)
{
    const float* xp = (const float*)d_in[0];
    const void*  wp = d_in[1];
    const float* sp = (const float*)d_in[2];
    const float* bp = (const float*)d_in[3];
    float*       op = (float*)d_out;

    cudaFuncSetAttribute(bitconv_hmma_kernel,
                         cudaFuncAttributeMaxDynamicSharedMemorySize, SMEM_TOTAL);

    probe_kernel<<<1, 256>>>(wp);
    prepass_kernel<<<(COUT * CIN * 9 + 255) / 256, 256>>>(wp);
    xprep_kernel<<<32 * HH, 256>>>(xp);

    dim3 grid(HH / 4, COUT / 64, 32);   // (row-quads, cogroups, batch)
    bitconv_hmma_kernel<<<grid, 256, SMEM_TOTAL>>>(sp, bp, op);
}